// round 12
// baseline (speedup 1.0000x reference)
#include <cuda_runtime.h>
#include <cuda_fp16.h>
#include <string.h>

#define NM 128
#define NM3 (NM * NM * NM)
#define NC 16
#define NPTS 100000
#define INV_SPACING 10.0f
#define NSLAB 8
#define SLABX (NM / NSLAB)              // 16 x-planes per slab
#define QC_PER_SLAB (NM3 / 4 / NSLAB)   // 65536 quad-cells per slab

// Scratch: mesh transposed to (x,y,z,c) fp16 layout. One cell = 32B.
__device__ ulonglong4 g_scratch[NM3];
// Counting-sort state (by ix, 128 bins)
__device__ int g_hist[NM];
__device__ int g_off[NM + 1];
__device__ int g_cursor[NM];
__device__ float g_spts[NPTS * 3];   // point coords in sorted order
__device__ int g_perm[NPTS];         // sorted position -> original index

static __device__ __forceinline__ unsigned h2u(__half2 h) {
    unsigned u; memcpy(&u, &h, 4); return u;
}
static __device__ __forceinline__ __half2 u2h(unsigned u) {
    __half2 h; memcpy(&h, &u, 4); return h;
}
static __device__ __forceinline__ unsigned long long pack64(unsigned lo, unsigned hi) {
    return (unsigned long long)lo | ((unsigned long long)hi << 32);
}
static __device__ __forceinline__ void st_cell_evict_last(ulonglong4* p, ulonglong4 v) {
    asm volatile("st.global.L2::evict_last.v4.b64 [%0], {%1,%2,%3,%4};"
                 :: "l"(p), "l"(v.x), "l"(v.y), "l"(v.z), "l"(v.w) : "memory");
}
static __device__ __forceinline__ ulonglong4 ld_cell_evict_last(const ulonglong4* p) {
    ulonglong4 r;
    asm("ld.global.nc.L2::evict_last.v4.b64 {%0,%1,%2,%3}, [%4];"
        : "=l"(r.x), "=l"(r.y), "=l"(r.z), "=l"(r.w) : "l"(p));
    return r;
}

// key = center x index of the stencil, matching interp's xs[1]
static __device__ __forceinline__ int point_key(float px) {
    return ((int)rintf(px * INV_SPACING)) & (NM - 1);
}

// --- sort kernels -----------------------------------------------------------
__global__ void zero_hist_kernel() {
    int t = threadIdx.x;
    if (t < NM) g_hist[t] = 0;
}

__global__ void hist_kernel(const float* __restrict__ points) {
    int i = blockIdx.x * blockDim.x + threadIdx.x;
    if (i >= NPTS) return;
    atomicAdd(&g_hist[point_key(points[i * 3])], 1);
}

__global__ void scan_kernel() {   // 1 block, 128 threads
    __shared__ int s[NM];
    int t = threadIdx.x;
    int v = g_hist[t];
    s[t] = v;
    __syncthreads();
#pragma unroll
    for (int d = 1; d < NM; d <<= 1) {
        int x = (t >= d) ? s[t - d] : 0;
        __syncthreads();
        s[t] += x;
        __syncthreads();
    }
    g_off[t + 1] = s[t];
    if (t == 0) g_off[0] = 0;
    g_cursor[t] = s[t] - v;   // exclusive prefix
}

__global__ void scatter_kernel(const float* __restrict__ points) {
    int i = blockIdx.x * blockDim.x + threadIdx.x;
    if (i >= NPTS) return;
    float x = points[i * 3 + 0];
    float y = points[i * 3 + 1];
    float z = points[i * 3 + 2];
    int pos = atomicAdd(&g_cursor[point_key(x)], 1);
    g_perm[pos] = i;
    g_spts[pos * 3 + 0] = x;
    g_spts[pos * 3 + 1] = y;
    g_spts[pos * 3 + 2] = z;
}

// --- transpose of one x-slab ------------------------------------------------
__global__ void transpose_slab_kernel(const float* __restrict__ in, int slab) {
    int q = slab * QC_PER_SLAB + blockIdx.x * blockDim.x + threadIdx.x;
    int cell0 = q * 4;

    float4 v[NC];
#pragma unroll
    for (int c = 0; c < NC; c++) {
        v[c] = __ldcs((const float4*)(in + (size_t)c * NM3 + cell0));
    }

#pragma unroll
    for (int z = 0; z < 4; z++) {
        float f[NC];
#pragma unroll
        for (int c = 0; c < NC; c++) {
            f[c] = (z == 0) ? v[c].x : (z == 1) ? v[c].y : (z == 2) ? v[c].z : v[c].w;
        }
        ulonglong4 cell;
        cell.x = pack64(h2u(__floats2half2_rn(f[0],  f[1])),
                        h2u(__floats2half2_rn(f[2],  f[3])));
        cell.y = pack64(h2u(__floats2half2_rn(f[4],  f[5])),
                        h2u(__floats2half2_rn(f[6],  f[7])));
        cell.z = pack64(h2u(__floats2half2_rn(f[8],  f[9])),
                        h2u(__floats2half2_rn(f[10], f[11])));
        cell.w = pack64(h2u(__floats2half2_rn(f[12], f[13])),
                        h2u(__floats2half2_rn(f[14], f[15])));
        st_cell_evict_last(&g_scratch[cell0 + z], cell);
    }
}

// --- interp of one x-bucket (R9 body, sorted inputs) ------------------------
__global__ void interp_bucket_kernel(float4* __restrict__ out, int bucket) {
    int start = g_off[bucket * SLABX];
    int end   = g_off[bucket * SLABX + SLABX];

    for (int i = start + blockIdx.x * blockDim.x + threadIdx.x; i < end;
         i += gridDim.x * blockDim.x) {
        float px = g_spts[i * 3 + 0] * INV_SPACING;
        float py = g_spts[i * 3 + 1] * INV_SPACING;
        float pz = g_spts[i * 3 + 2] * INV_SPACING;
        int op = g_perm[i];

        float rx = rintf(px), ry = rintf(py), rz = rintf(pz);
        float dx = px - rx, dy = py - ry, dz = pz - rz;
        int ix = (int)rx, iy = (int)ry, iz = (int)rz;

        float wx[3], wy[3], wz[3];
        {
            float a;
            a = 2.0f * dx - 1.0f; wx[0] = a * a * 0.125f;
            wx[1] = 0.75f - dx * dx;
            a = 2.0f * dx + 1.0f; wx[2] = a * a * 0.125f;

            a = 2.0f * dy - 1.0f; wy[0] = a * a * 0.125f;
            wy[1] = 0.75f - dy * dy;
            a = 2.0f * dy + 1.0f; wy[2] = a * a * 0.125f;

            a = 2.0f * dz - 1.0f; wz[0] = a * a * 0.125f;
            wz[1] = 0.75f - dz * dz;
            a = 2.0f * dz + 1.0f; wz[2] = a * a * 0.125f;
        }

        int xs[3], ys[3], zs[3];
        xs[0] = (ix + 127) & (NM - 1); xs[1] = ix & (NM - 1); xs[2] = (ix + 129) & (NM - 1);
        ys[0] = (iy + 127) & (NM - 1); ys[1] = iy & (NM - 1); ys[2] = (iy + 129) & (NM - 1);
        zs[0] = (iz + 127) & (NM - 1); zs[1] = iz & (NM - 1); zs[2] = (iz + 129) & (NM - 1);

        float acc[NC];
#pragma unroll
        for (int c = 0; c < NC; c++) acc[c] = 0.0f;

#pragma unroll
        for (int ox = 0; ox < 3; ox++) {
#pragma unroll
            for (int oy = 0; oy < 3; oy++) {
                float wxy = wx[ox] * wy[oy];
                int rowbase = (xs[ox] * NM + ys[oy]) * NM;
#pragma unroll
                for (int oz = 0; oz < 3; oz++) {
                    float w = wxy * wz[oz];
                    ulonglong4 raw = ld_cell_evict_last(&g_scratch[rowbase + zs[oz]]);
                    unsigned long long qd[4] = {raw.x, raw.y, raw.z, raw.w};
#pragma unroll
                    for (int j = 0; j < 4; j++) {
                        float2 f0 = __half22float2(u2h((unsigned)qd[j]));
                        float2 f1 = __half22float2(u2h((unsigned)(qd[j] >> 32)));
                        acc[j * 4 + 0] += w * f0.x;
                        acc[j * 4 + 1] += w * f0.y;
                        acc[j * 4 + 2] += w * f1.x;
                        acc[j * 4 + 3] += w * f1.y;
                    }
                }
            }
        }

        float4* o = out + (size_t)op * 4;
        __stcs(o + 0, make_float4(acc[0],  acc[1],  acc[2],  acc[3]));
        __stcs(o + 1, make_float4(acc[4],  acc[5],  acc[6],  acc[7]));
        __stcs(o + 2, make_float4(acc[8],  acc[9],  acc[10], acc[11]));
        __stcs(o + 3, make_float4(acc[12], acc[13], acc[14], acc[15]));
    }
}

extern "C" void kernel_launch(void* const* d_in, const int* in_sizes, int n_in,
                              void* d_out, int out_size) {
    const float* mesh = (const float*)d_in[0];    // (16, 128, 128, 128) f32
    const float* points = (const float*)d_in[1];  // (100000, 3) f32
    float4* out = (float4*)d_out;                 // (100000, 16) f32

    // Forked stream + events for transpose/interp pipelining. Created fresh
    // per call (kernel_launch runs only for correctness + capture); streams
    // and events hold no device memory.
    cudaStream_t s2;
    cudaStreamCreate(&s2);
    cudaEvent_t ev[NSLAB], evDone;
    for (int k = 0; k < NSLAB; k++)
        cudaEventCreateWithFlags(&ev[k], cudaEventDisableTiming);
    cudaEventCreateWithFlags(&evDone, cudaEventDisableTiming);

    // Sort points by center x-index (main stream)
    zero_hist_kernel<<<1, 128>>>();
    hist_kernel<<<(NPTS + 255) / 256, 256>>>(points);
    scan_kernel<<<1, 128>>>();
    scatter_kernel<<<(NPTS + 255) / 256, 256>>>(points);

    // Transpose slabs in wrap-friendly order; event after each.
    const int order[NSLAB] = {7, 0, 1, 2, 3, 4, 5, 6};
    for (int k = 0; k < NSLAB; k++) {
        transpose_slab_kernel<<<QC_PER_SLAB / 256, 256>>>(mesh, order[k]);
        cudaEventRecord(ev[k], 0);
    }

    // Interp buckets on the forked stream. Bucket b needs slabs b-1, b, b+1
    // (mod 8): ready after sequence index b+2 (clamped to 7 for b >= 6
    // because slab b+1 lands at the end of the T7,T0..T6 order).
    for (int b = 0; b < NSLAB; b++) {
        int w = (b <= 5) ? (b + 2) : 7;
        cudaStreamWaitEvent(s2, ev[w], 0);
        interp_bucket_kernel<<<96, 256, 0, s2>>>(out, b);
    }
    cudaEventRecord(evDone, s2);
    cudaStreamWaitEvent(0, evDone, 0);
}

// round 13
// speedup vs baseline: 2.2145x; 2.2145x over previous
#include <cuda_runtime.h>
#include <cuda_fp16.h>
#include <string.h>

#define NM 128
#define NM3 (NM * NM * NM)
#define NC 16
#define NPTS 100000
#define INV_SPACING 10.0f

// Two half-channel scratch buffers, (x,y,z, ch-half) fp16 layout.
// One half-cell = 8 halfs = 16 bytes; stored as 32B pairs (z even/odd) so
// transpose stores can carry L2::evict_last (needs 256-bit access).
// 33.5 MB each -> each is only ~27% of L2.
__device__ ulonglong4 g_scrA[NM3 / 2];   // channels 0..7
__device__ ulonglong4 g_scrB[NM3 / 2];   // channels 8..15

static __device__ __forceinline__ unsigned h2u(__half2 h) {
    unsigned u; memcpy(&u, &h, 4); return u;
}
static __device__ __forceinline__ __half2 u2h(unsigned u) {
    __half2 h; memcpy(&h, &u, 4); return h;
}
static __device__ __forceinline__ unsigned long long pack64(unsigned lo, unsigned hi) {
    return (unsigned long long)lo | ((unsigned long long)hi << 32);
}
static __device__ __forceinline__ void st_pair_evict_last(ulonglong4* p, ulonglong4 v) {
    asm volatile("st.global.L2::evict_last.v4.b64 [%0], {%1,%2,%3,%4};"
                 :: "l"(p), "l"(v.x), "l"(v.y), "l"(v.z), "l"(v.w) : "memory");
}

// ---------------------------------------------------------------------------
// Transpose one channel-half: (c, cell)f32 -> (cell, c-half)f16.
// One thread per 8 consecutive z-cells: 16 LDG.128.cs reads, 4 STG.256
// evict_last writes (each covers 2 cells).
// ---------------------------------------------------------------------------
__global__ void transpose_half_kernel(const float* __restrict__ in, int cbase,
                                      ulonglong4* __restrict__ dst) {
    int t = blockIdx.x * blockDim.x + threadIdx.x;   // 0 .. NM3/8-1
    int cell0 = t * 8;

    float4 v[8][2];
#pragma unroll
    for (int c = 0; c < 8; c++) {
        const float4* p = (const float4*)(in + (size_t)(cbase + c) * NM3 + cell0);
        v[c][0] = __ldcs(p);
        v[c][1] = __ldcs(p + 1);
    }

#pragma unroll
    for (int k = 0; k < 4; k++) {        // z-pair (2k, 2k+1)
        int h = k >> 1;                  // which float4 half
        float f0[8], f1[8];
#pragma unroll
        for (int c = 0; c < 8; c++) {
            float4 q = v[c][h];
            if ((k & 1) == 0) { f0[c] = q.x; f1[c] = q.y; }
            else              { f0[c] = q.z; f1[c] = q.w; }
        }
        ulonglong4 o;
        o.x = pack64(h2u(__floats2half2_rn(f0[0], f0[1])),
                     h2u(__floats2half2_rn(f0[2], f0[3])));
        o.y = pack64(h2u(__floats2half2_rn(f0[4], f0[5])),
                     h2u(__floats2half2_rn(f0[6], f0[7])));
        o.z = pack64(h2u(__floats2half2_rn(f1[0], f1[1])),
                     h2u(__floats2half2_rn(f1[2], f1[3])));
        o.w = pack64(h2u(__floats2half2_rn(f1[4], f1[5])),
                     h2u(__floats2half2_rn(f1[6], f1[7])));
        st_pair_evict_last(&dst[t * 4 + k], o);
    }
}

// ---------------------------------------------------------------------------
// Interp one channel-half: 1 thread per point, 27 independent 16B taps
// (8 channels each), fp32 weights/accum, 32B output per point.
// ---------------------------------------------------------------------------
__global__ void interp_half_kernel(const float* __restrict__ points,
                                   const uint4* __restrict__ scr,
                                   float4* __restrict__ out, int ohalf) {
    int p = blockIdx.x * blockDim.x + threadIdx.x;
    if (p >= NPTS) return;

    float px = points[p * 3 + 0] * INV_SPACING;
    float py = points[p * 3 + 1] * INV_SPACING;
    float pz = points[p * 3 + 2] * INV_SPACING;

    float rx = rintf(px), ry = rintf(py), rz = rintf(pz);
    float dx = px - rx, dy = py - ry, dz = pz - rz;
    int ix = (int)rx, iy = (int)ry, iz = (int)rz;

    float wx[3], wy[3], wz[3];
    {
        float a;
        a = 2.0f * dx - 1.0f; wx[0] = a * a * 0.125f;
        wx[1] = 0.75f - dx * dx;
        a = 2.0f * dx + 1.0f; wx[2] = a * a * 0.125f;

        a = 2.0f * dy - 1.0f; wy[0] = a * a * 0.125f;
        wy[1] = 0.75f - dy * dy;
        a = 2.0f * dy + 1.0f; wy[2] = a * a * 0.125f;

        a = 2.0f * dz - 1.0f; wz[0] = a * a * 0.125f;
        wz[1] = 0.75f - dz * dz;
        a = 2.0f * dz + 1.0f; wz[2] = a * a * 0.125f;
    }

    int xs[3], ys[3], zs[3];
    xs[0] = (ix + 127) & (NM - 1); xs[1] = ix & (NM - 1); xs[2] = (ix + 129) & (NM - 1);
    ys[0] = (iy + 127) & (NM - 1); ys[1] = iy & (NM - 1); ys[2] = (iy + 129) & (NM - 1);
    zs[0] = (iz + 127) & (NM - 1); zs[1] = iz & (NM - 1); zs[2] = (iz + 129) & (NM - 1);

    float acc[8];
#pragma unroll
    for (int c = 0; c < 8; c++) acc[c] = 0.0f;

#pragma unroll
    for (int ox = 0; ox < 3; ox++) {
#pragma unroll
        for (int oy = 0; oy < 3; oy++) {
            float wxy = wx[ox] * wy[oy];
            int rowbase = (xs[ox] * NM + ys[oy]) * NM;
#pragma unroll
            for (int oz = 0; oz < 3; oz++) {
                float w = wxy * wz[oz];
                uint4 raw = __ldg(&scr[rowbase + zs[oz]]);
                float2 f0 = __half22float2(u2h(raw.x));
                float2 f1 = __half22float2(u2h(raw.y));
                float2 f2 = __half22float2(u2h(raw.z));
                float2 f3 = __half22float2(u2h(raw.w));
                acc[0] += w * f0.x; acc[1] += w * f0.y;
                acc[2] += w * f1.x; acc[3] += w * f1.y;
                acc[4] += w * f2.x; acc[5] += w * f2.y;
                acc[6] += w * f3.x; acc[7] += w * f3.y;
            }
        }
    }

    float4* o = out + (size_t)p * 4 + ohalf;
    __stcs(o + 0, make_float4(acc[0], acc[1], acc[2], acc[3]));
    __stcs(o + 1, make_float4(acc[4], acc[5], acc[6], acc[7]));
}

extern "C" void kernel_launch(void* const* d_in, const int* in_sizes, int n_in,
                              void* d_out, int out_size) {
    const float* mesh = (const float*)d_in[0];    // (16, 128, 128, 128) f32
    const float* points = (const float*)d_in[1];  // (100000, 3) f32
    float4* out = (float4*)d_out;                 // (100000, 16) f32

    ulonglong4* scrA; cudaGetSymbolAddress((void**)&scrA, g_scrA);
    ulonglong4* scrB; cudaGetSymbolAddress((void**)&scrB, g_scrB);

    cudaStream_t s2;
    cudaStreamCreate(&s2);
    cudaEvent_t evA, evB, evDone;
    cudaEventCreateWithFlags(&evA, cudaEventDisableTiming);
    cudaEventCreateWithFlags(&evB, cudaEventDisableTiming);
    cudaEventCreateWithFlags(&evDone, cudaEventDisableTiming);

    const int tThreads = 256, tBlocks = (NM3 / 8) / tThreads;      // 1024
    const int iThreads = 256, iBlocks = (NPTS + iThreads - 1) / iThreads;  // 391

    // Main stream: transpose half A, then half B.
    transpose_half_kernel<<<tBlocks, tThreads>>>(mesh, 0, scrA);
    cudaEventRecord(evA, 0);
    transpose_half_kernel<<<tBlocks, tThreads>>>(mesh, 8, scrB);
    cudaEventRecord(evB, 0);

    // Forked stream: interp A overlaps transpose B; interp B after.
    cudaStreamWaitEvent(s2, evA, 0);
    interp_half_kernel<<<iBlocks, iThreads, 0, s2>>>(points, (const uint4*)scrA, out, 0);
    cudaStreamWaitEvent(s2, evB, 0);
    interp_half_kernel<<<iBlocks, iThreads, 0, s2>>>(points, (const uint4*)scrB, out, 2);
    cudaEventRecord(evDone, s2);
    cudaStreamWaitEvent(0, evDone, 0);
}